// round 7
// baseline (speedup 1.0000x reference)
#include <cuda_runtime.h>

// BlockLinear: y[b, o] = sum_{k<16} x[b, o*16+k] * w[o, k]
// B=8192, OUT=2048, BLOCK=16.
//
// R6 finding: bandwidth pinned at ~6.86 TB/s across 3 kernel shapes = the
// path-independent LTS chip cap (~6300 B/cyc). Remaining gap to service time
// (~155us) is wave quantization: 4096 blocks / 740 slots = 5.54 ragged waves.
// R7: persistent 740-block grid, per-warp grid-stride over 65536 fine tiles
// (G=8 rows x 32 outputs = 16KB each). No wave transitions, ~2us tail.

#define OUT_FEATURES 2048
#define B_ROWS 8192
#define G 8                          // batch rows per tile
#define BDIM 256
#define WARPS_PER_BLK (BDIM / 32)
#define O_TILES (OUT_FEATURES / 32)                      // 64
#define TOTAL_TILES ((B_ROWS / G) * O_TILES)             // 65536
#define NBLOCKS (148 * 5)                                // 740 persistent blocks
#define GLOBAL_WARPS (NBLOCKS * WARPS_PER_BLK)           // 5920

__global__ __launch_bounds__(BDIM, 5) void block_linear_kernel(
    const float4* __restrict__ x4,   // x as float4
    const float4* __restrict__ w4,   // weight as float4: w4[o*4 + c]
    float* __restrict__ out)
{
    const int lane = threadIdx.x & 31;
    const int gw0  = blockIdx.x * WARPS_PER_BLK + (threadIdx.x >> 5);
    const int c = lane & 3;    // chunk index (4 float4 chunks per output)
    const int r = lane >> 2;   // row-within-8 group

    for (int wt = gw0; wt < TOTAL_TILES; wt += GLOBAL_WARPS) {
        const int o_tile = (wt & (O_TILES - 1)) << 5;   // 32 consecutive outputs
        const int b0     = (wt >> 6) * G;               // 8 consecutive batch rows

        // Weights for this tile's 32 outputs, distributed across lanes
        // (L2-resident; 4 coalesced LDGs per 32 x-LDGs — negligible).
        const float4 wv0 = __ldg(&w4[(o_tile + 0 * 8 + r) * 4 + c]);
        const float4 wv1 = __ldg(&w4[(o_tile + 1 * 8 + r) * 4 + c]);
        const float4 wv2 = __ldg(&w4[(o_tile + 2 * 8 + r) * 4 + c]);
        const float4 wv3 = __ldg(&w4[(o_tile + 3 * 8 + r) * 4 + c]);

        #pragma unroll
        for (int g = 0; g < G; g++) {
            const int b = b0 + g;
            const long long xbase = ((long long)b * OUT_FEATURES + o_tile) << 2;

            // Perfectly coalesced: 512B contiguous per warp-load.
            const float4 xv0 = __ldcs(&x4[xbase + 0 * 32 + lane]);
            const float4 xv1 = __ldcs(&x4[xbase + 1 * 32 + lane]);
            const float4 xv2 = __ldcs(&x4[xbase + 2 * 32 + lane]);
            const float4 xv3 = __ldcs(&x4[xbase + 3 * 32 + lane]);

            float p0 = xv0.x * wv0.x + xv0.y * wv0.y + xv0.z * wv0.z + xv0.w * wv0.w;
            float p1 = xv1.x * wv1.x + xv1.y * wv1.y + xv1.z * wv1.z + xv1.w * wv1.w;
            float p2 = xv2.x * wv2.x + xv2.y * wv2.y + xv2.z * wv2.z + xv2.w * wv2.w;
            float p3 = xv3.x * wv3.x + xv3.y * wv3.y + xv3.z * wv3.z + xv3.w * wv3.w;

            // Reduce the 4 chunk-lanes of each output.
            p0 += __shfl_xor_sync(0xFFFFFFFFu, p0, 1);
            p1 += __shfl_xor_sync(0xFFFFFFFFu, p1, 1);
            p2 += __shfl_xor_sync(0xFFFFFFFFu, p2, 1);
            p3 += __shfl_xor_sync(0xFFFFFFFFu, p3, 1);
            p0 += __shfl_xor_sync(0xFFFFFFFFu, p0, 2);
            p1 += __shfl_xor_sync(0xFFFFFFFFu, p1, 2);
            p2 += __shfl_xor_sync(0xFFFFFFFFu, p2, 2);
            p3 += __shfl_xor_sync(0xFFFFFFFFu, p3, 2);

            // Lane i stores output (i%4)*8 + i/4 — bijective over the tile,
            // one contiguous 128B line per warp.
            const float v = (c == 0) ? p0 : (c == 1) ? p1 : (c == 2) ? p2 : p3;
            __stcs(&out[(long long)b * OUT_FEATURES + o_tile + c * 8 + r], v);
        }
    }
}

extern "C" void kernel_launch(void* const* d_in, const int* in_sizes, int n_in,
                              void* d_out, int out_size)
{
    const float4* x4 = (const float4*)d_in[0];
    const float4* w4 = (const float4*)d_in[1];
    float* out = (float*)d_out;

    block_linear_kernel<<<NBLOCKS, BDIM>>>(x4, w4, out);
}

// round 8
// speedup vs baseline: 1.0057x; 1.0057x over previous
#include <cuda_runtime.h>

// BlockLinear: y[b, o] = sum_{k<16} x[b, o*16+k] * w[o, k]
// B=8192, OUT=2048, BLOCK=16.
//
// R7 finding: kernel time == traffic / delivered-BW exactly (no scheduling
// slack); 3 kernel shapes all pin at ~6.87 TB/s => memory-system ceiling.
// Persistent grid regressed ~2us -> revert to R6 shape (grid 4096).
// R8: single experiment on top of R6 — L2::256B fetch granularity on the
// dense x stream (fewer L2 requests, longer DRAM bursts; zero waste traffic).

#define OUT_FEATURES 2048
#define B_ROWS 8192
#define G 16                        // batch rows per warp tile
#define BDIM 256
#define WARPS_PER_BLK (BDIM / 32)
#define O_TILES (OUT_FEATURES / 32)          // 64
#define NBLOCKS ((B_ROWS / G) * O_TILES / WARPS_PER_BLK)   // 4096

__device__ __forceinline__ float4 ldcs_256B(const float4* p) {
    float4 v;
    asm volatile("ld.global.cs.L2::256B.v4.f32 {%0,%1,%2,%3}, [%4];"
                 : "=f"(v.x), "=f"(v.y), "=f"(v.z), "=f"(v.w)
                 : "l"(p));
    return v;
}

__global__ __launch_bounds__(BDIM, 5) void block_linear_kernel(
    const float4* __restrict__ x4,   // x as float4
    const float4* __restrict__ w4,   // weight as float4: w4[o*4 + c]
    float* __restrict__ out)
{
    const int lane = threadIdx.x & 31;
    const int w    = blockIdx.x * WARPS_PER_BLK + (threadIdx.x >> 5);
    const int o_tile = (w & (O_TILES - 1)) << 5;   // 32 consecutive outputs
    const int b0     = (w >> 6) << 4;              // 16 consecutive batch rows

    const int c = lane & 3;    // chunk index within an output (4 float4 = 16 floats)
    const int r = lane >> 2;   // row-within-8 group

    // Weights for this warp's 32 outputs, distributed across lanes.
    const float4 wv0 = __ldg(&w4[(o_tile + 0 * 8 + r) * 4 + c]);
    const float4 wv1 = __ldg(&w4[(o_tile + 1 * 8 + r) * 4 + c]);
    const float4 wv2 = __ldg(&w4[(o_tile + 2 * 8 + r) * 4 + c]);
    const float4 wv3 = __ldg(&w4[(o_tile + 3 * 8 + r) * 4 + c]);

    #pragma unroll
    for (int g = 0; g < G; g++) {
        const int b = b0 + g;
        const long long xbase = ((long long)b * OUT_FEATURES + o_tile) << 2;

        // Perfectly coalesced: 512B contiguous per warp-load, 256B L2 lines.
        const float4 xv0 = ldcs_256B(&x4[xbase + 0 * 32 + lane]);
        const float4 xv1 = ldcs_256B(&x4[xbase + 1 * 32 + lane]);
        const float4 xv2 = ldcs_256B(&x4[xbase + 2 * 32 + lane]);
        const float4 xv3 = ldcs_256B(&x4[xbase + 3 * 32 + lane]);

        float p0 = xv0.x * wv0.x + xv0.y * wv0.y + xv0.z * wv0.z + xv0.w * wv0.w;
        float p1 = xv1.x * wv1.x + xv1.y * wv1.y + xv1.z * wv1.z + xv1.w * wv1.w;
        float p2 = xv2.x * wv2.x + xv2.y * wv2.y + xv2.z * wv2.z + xv2.w * wv2.w;
        float p3 = xv3.x * wv3.x + xv3.y * wv3.y + xv3.z * wv3.z + xv3.w * wv3.w;

        // Reduce the 4 chunk-lanes of each output.
        p0 += __shfl_xor_sync(0xFFFFFFFFu, p0, 1);
        p1 += __shfl_xor_sync(0xFFFFFFFFu, p1, 1);
        p2 += __shfl_xor_sync(0xFFFFFFFFu, p2, 1);
        p3 += __shfl_xor_sync(0xFFFFFFFFu, p3, 1);
        p0 += __shfl_xor_sync(0xFFFFFFFFu, p0, 2);
        p1 += __shfl_xor_sync(0xFFFFFFFFu, p1, 2);
        p2 += __shfl_xor_sync(0xFFFFFFFFu, p2, 2);
        p3 += __shfl_xor_sync(0xFFFFFFFFu, p3, 2);

        // Lane i stores output (i%4)*8 + i/4 — bijective over the 32-output
        // tile, one contiguous 128B line per warp.
        const float v = (c == 0) ? p0 : (c == 1) ? p1 : (c == 2) ? p2 : p3;
        __stcs(&out[(long long)b * OUT_FEATURES + o_tile + c * 8 + r], v);
    }
}

extern "C" void kernel_launch(void* const* d_in, const int* in_sizes, int n_in,
                              void* d_out, int out_size)
{
    const float4* x4 = (const float4*)d_in[0];
    const float4* w4 = (const float4*)d_in[1];
    float* out = (float*)d_out;

    block_linear_kernel<<<NBLOCKS, BDIM>>>(x4, w4, out);
}

// round 9
// speedup vs baseline: 1.0200x; 1.0142x over previous
#include <cuda_runtime.h>

// BlockLinear: y[b, o] = sum_{k<16} x[b, o*16+k] * w[o, k]
// B=8192, OUT=2048, BLOCK=16.
//
// R8 finding: L2::256B raised delivered BW to 6.92 TB/s (87.4% DRAM, best
// ncu-dur 162.9us); harness delta was noise. We are at the memory-system
// ceiling: wall time == traffic/BW exactly.
// R9: keep R8 config; route x through the non-coherent read-only path
// (ld.global.nc.cs.L2::256B) to shave LSU/L2 request overhead. Final polish.

#define OUT_FEATURES 2048
#define B_ROWS 8192
#define G 16                        // batch rows per warp tile
#define BDIM 256
#define WARPS_PER_BLK (BDIM / 32)
#define O_TILES (OUT_FEATURES / 32)          // 64
#define NBLOCKS ((B_ROWS / G) * O_TILES / WARPS_PER_BLK)   // 4096

__device__ __forceinline__ float4 ldnc_cs_256B(const float4* p) {
    float4 v;
    asm volatile("ld.global.nc.cs.L2::256B.v4.f32 {%0,%1,%2,%3}, [%4];"
                 : "=f"(v.x), "=f"(v.y), "=f"(v.z), "=f"(v.w)
                 : "l"(p));
    return v;
}

__global__ __launch_bounds__(BDIM, 5) void block_linear_kernel(
    const float4* __restrict__ x4,   // x as float4
    const float4* __restrict__ w4,   // weight as float4: w4[o*4 + c]
    float* __restrict__ out)
{
    const int lane = threadIdx.x & 31;
    const int w    = blockIdx.x * WARPS_PER_BLK + (threadIdx.x >> 5);
    const int o_tile = (w & (O_TILES - 1)) << 5;   // 32 consecutive outputs
    const int b0     = (w >> 6) << 4;              // 16 consecutive batch rows

    const int c = lane & 3;    // chunk index within an output (4 float4 = 16 floats)
    const int r = lane >> 2;   // row-within-8 group

    // Weights for this warp's 32 outputs, distributed across lanes (L2-resident).
    const float4 wv0 = __ldg(&w4[(o_tile + 0 * 8 + r) * 4 + c]);
    const float4 wv1 = __ldg(&w4[(o_tile + 1 * 8 + r) * 4 + c]);
    const float4 wv2 = __ldg(&w4[(o_tile + 2 * 8 + r) * 4 + c]);
    const float4 wv3 = __ldg(&w4[(o_tile + 3 * 8 + r) * 4 + c]);

    #pragma unroll
    for (int g = 0; g < G; g++) {
        const int b = b0 + g;
        const long long xbase = ((long long)b * OUT_FEATURES + o_tile) << 2;

        // Perfectly coalesced: 512B contiguous per warp-load, 256B L2 lines,
        // non-coherent read-only path, evict-first.
        const float4 xv0 = ldnc_cs_256B(&x4[xbase + 0 * 32 + lane]);
        const float4 xv1 = ldnc_cs_256B(&x4[xbase + 1 * 32 + lane]);
        const float4 xv2 = ldnc_cs_256B(&x4[xbase + 2 * 32 + lane]);
        const float4 xv3 = ldnc_cs_256B(&x4[xbase + 3 * 32 + lane]);

        float p0 = xv0.x * wv0.x + xv0.y * wv0.y + xv0.z * wv0.z + xv0.w * wv0.w;
        float p1 = xv1.x * wv1.x + xv1.y * wv1.y + xv1.z * wv1.z + xv1.w * wv1.w;
        float p2 = xv2.x * wv2.x + xv2.y * wv2.y + xv2.z * wv2.z + xv2.w * wv2.w;
        float p3 = xv3.x * wv3.x + xv3.y * wv3.y + xv3.z * wv3.z + xv3.w * wv3.w;

        // Reduce the 4 chunk-lanes of each output.
        p0 += __shfl_xor_sync(0xFFFFFFFFu, p0, 1);
        p1 += __shfl_xor_sync(0xFFFFFFFFu, p1, 1);
        p2 += __shfl_xor_sync(0xFFFFFFFFu, p2, 1);
        p3 += __shfl_xor_sync(0xFFFFFFFFu, p3, 1);
        p0 += __shfl_xor_sync(0xFFFFFFFFu, p0, 2);
        p1 += __shfl_xor_sync(0xFFFFFFFFu, p1, 2);
        p2 += __shfl_xor_sync(0xFFFFFFFFu, p2, 2);
        p3 += __shfl_xor_sync(0xFFFFFFFFu, p3, 2);

        // Lane i stores output (i%4)*8 + i/4 — bijective over the 32-output
        // tile, one contiguous 128B line per warp.
        const float v = (c == 0) ? p0 : (c == 1) ? p1 : (c == 2) ? p2 : p3;
        __stcs(&out[(long long)b * OUT_FEATURES + o_tile + c * 8 + r], v);
    }
}

extern "C" void kernel_launch(void* const* d_in, const int* in_sizes, int n_in,
                              void* d_out, int out_size)
{
    const float4* x4 = (const float4*)d_in[0];
    const float4* w4 = (const float4*)d_in[1];
    float* out = (float*)d_out;

    block_linear_kernel<<<NBLOCKS, BDIM>>>(x4, w4, out);
}